// round 17
// baseline (speedup 1.0000x reference)
#include <cuda_runtime.h>
#include <cuda_fp16.h>
#include <cstdint>

#define B_  4
#define S_  2048
#define D_  1024
#define H_  16
#define DK_ 64
#define M_  (B_*S_)     // 8192
#define BH_ (B_*H_)     // 64

// fp16 operands
__device__ __half g_Xf[M_*D_];                   // X
__device__ __half g_Wf[3*D_*D_];                 // W qkv, [z][k][n]
__device__ __half g_Qf[BH_*S_*DK_];              // Q (scale folded)
__device__ __half g_Kf[BH_*S_*DK_];
__device__ __half g_Vf[BH_*S_*DK_];
__device__ __half g_Of[BH_*S_*DK_];
__device__ __half g_WOf[D_*D_];

// ---------------------------------------------------------------------------
// helpers
// ---------------------------------------------------------------------------
__device__ __forceinline__ unsigned f16pack(float x, float y) {
    __half2 t = __floats2half2_rn(x, y);
    return *reinterpret_cast<unsigned*>(&t);
}
__device__ __forceinline__ unsigned sma(const void* p) {
    return (unsigned)__cvta_generic_to_shared(p);
}
__device__ __forceinline__ void mma_f16(float* c, const unsigned* a, unsigned b0, unsigned b1) {
    asm("mma.sync.aligned.m16n8k16.row.col.f32.f16.f16.f32 "
        "{%0,%1,%2,%3}, {%4,%5,%6,%7}, {%8,%9}, {%0,%1,%2,%3};"
        : "+f"(c[0]), "+f"(c[1]), "+f"(c[2]), "+f"(c[3])
        : "r"(a[0]), "r"(a[1]), "r"(a[2]), "r"(a[3]), "r"(b0), "r"(b1));
}
__device__ __forceinline__ void ldsm_x4(unsigned* r, unsigned a) {
    asm volatile("ldmatrix.sync.aligned.m8n8.x4.shared.b16 {%0,%1,%2,%3}, [%4];"
                 : "=r"(r[0]), "=r"(r[1]), "=r"(r[2]), "=r"(r[3]) : "r"(a));
}
__device__ __forceinline__ void ldsm_x4t(unsigned* r, unsigned a) {
    asm volatile("ldmatrix.sync.aligned.m8n8.x4.trans.shared.b16 {%0,%1,%2,%3}, [%4];"
                 : "=r"(r[0]), "=r"(r[1]), "=r"(r[2]), "=r"(r[3]) : "r"(a));
}
#define CP16(dst, src) \
    asm volatile("cp.async.cg.shared.global [%0], [%1], 16;" :: "r"(dst), "l"(src) : "memory")
#define CPCOMMIT() asm volatile("cp.async.commit_group;" ::: "memory")
#define CPWAIT1()  asm volatile("cp.async.wait_group 1;" ::: "memory")
#define CPWAIT0()  asm volatile("cp.async.wait_group 0;" ::: "memory")

// ---------------------------------------------------------------------------
// Convert kernels (fp32 -> fp16)
// ---------------------------------------------------------------------------
__global__ __launch_bounds__(256) void conv_x_kernel(const float* __restrict__ src) {
    size_t i = (size_t)blockIdx.x * 256 + threadIdx.x;
    float4 v0 = *(const float4*)(src + i * 8);
    float4 v1 = *(const float4*)(src + i * 8 + 4);
    *(uint4*)(g_Xf + i * 8) = make_uint4(
        f16pack(v0.x, v0.y), f16pack(v0.z, v0.w),
        f16pack(v1.x, v1.y), f16pack(v1.z, v1.w));
}
__global__ __launch_bounds__(256) void conv_wqkv_kernel(
    const float* __restrict__ WQ, const float* __restrict__ WK, const float* __restrict__ WV)
{
    unsigned i = blockIdx.x * 256 + threadIdx.x;
    int o8 = (i & 7) * 8;
    int d  = (i >> 3) & 1023;
    int h  = (i >> 13) & 15;
    int z  = i >> 17;
    const float* src = ((z == 0) ? WQ : (z == 1) ? WK : WV) + ((size_t)h * D_ + d) * DK_ + o8;
    float4 v0 = *(const float4*)(src);
    float4 v1 = *(const float4*)(src + 4);
    size_t dst = (size_t)z * D_ * D_ + (size_t)d * D_ + h * 64 + o8;
    *(uint4*)(g_Wf + dst) = make_uint4(
        f16pack(v0.x, v0.y), f16pack(v0.z, v0.w),
        f16pack(v1.x, v1.y), f16pack(v1.z, v1.w));
}
__global__ __launch_bounds__(256) void conv_wo_kernel(const float* __restrict__ src) {
    size_t i = (size_t)blockIdx.x * 256 + threadIdx.x;
    float4 v0 = *(const float4*)(src + i * 8);
    float4 v1 = *(const float4*)(src + i * 8 + 4);
    *(uint4*)(g_WOf + i * 8) = make_uint4(
        f16pack(v0.x, v0.y), f16pack(v0.z, v0.w),
        f16pack(v1.x, v1.y), f16pack(v1.z, v1.w));
}

// ---------------------------------------------------------------------------
// GEMM: 128x128 tile, 8 warps 4m x 2n, BK=64 (halved barrier cadence),
// cp.async double-buffered.
// MODE 0 = qkv: A = g_Xf, B = g_Wf[z]; epilogue -> Q/K/V fp16
// MODE 1 = out: A = g_Of, B = g_WOf;   epilogue -> fp32
// ---------------------------------------------------------------------------
#define AS_LD 72                        // 144B rows (9x16B, odd -> conflict-free)
#define BS_LD 136
#define A_STAGE (128 * AS_LD)           // 9216 elems
#define GB_OFF  (2 * A_STAGE)
#define GB_STAGE (64 * BS_LD)           // 8704 elems
#define GEMM_SMEM ((2 * A_STAGE + 2 * GB_STAGE) * 2)   // 71680 B

template<int MODE>
__global__ __launch_bounds__(256, 2) void gemm_kernel(float* __restrict__ Out) {
    extern __shared__ __align__(16) char smg[];
    const unsigned sb = sma(smg);
    const int z = (MODE == 0) ? blockIdx.z : 0;
    const __half* Bsrc = (MODE == 0) ? g_Wf + (size_t)z * D_ * D_ : g_WOf;

    const int tid = threadIdx.x, wid = tid >> 5, lane = tid & 31;
    const int wm = wid & 3, wn = wid >> 2;
    const int m0 = blockIdx.y * 128, n0 = blockIdx.x * 128;

    float oc[2][8][4];
#pragma unroll
    for (int a = 0; a < 2; a++)
#pragma unroll
        for (int b = 0; b < 8; b++)
#pragma unroll
            for (int c = 0; c < 4; c++) oc[a][b][c] = 0.f;

    auto stage = [&](int k0, int st) {
#pragma unroll
        for (int u = 0; u < 4; u++) {             // A: 128x64
            int rem = tid + u * 256;
            int row = rem >> 3, ch = (rem & 7) * 8;
            const __half* src;
            if (MODE == 0) {
                src = g_Xf + (size_t)(m0 + row) * D_ + k0 + ch;
            } else {
                int m = m0 + row, b = m >> 11, s = m & (S_ - 1);
                src = g_Of + ((size_t)(b * H_ + (k0 >> 6)) * S_ + s) * DK_ + ch;
            }
            CP16(sb + (st * A_STAGE + row * AS_LD + ch) * 2, src);
        }
#pragma unroll
        for (int u = 0; u < 4; u++) {             // B: 64x128
            int rem = tid + u * 256;
            int row = rem >> 4, ch = (rem & 15) * 8;
            const __half* src = Bsrc + (size_t)(k0 + row) * D_ + n0 + ch;
            CP16(sb + (GB_OFF + st * GB_STAGE + row * BS_LD + ch) * 2, src);
        }
    };

    stage(0, 0); CPCOMMIT();

    const int arow = lane & 15, acol = (lane >> 4) * 8;
    const int brow = lane & 15, bcol = (lane & 16) >> 1;

    int st = 0;
    for (int k0 = 0; k0 < D_; k0 += 64) {
        if (k0 + 64 < D_) { stage(k0 + 64, st ^ 1); CPCOMMIT(); CPWAIT1(); }
        else CPWAIT0();
        __syncthreads();
#pragma unroll
        for (int h = 0; h < 4; h++) {
            unsigned ah[2][4];
#pragma unroll
            for (int mi = 0; mi < 2; mi++) {
                unsigned ao = sb + (st * A_STAGE + (wm * 32 + mi * 16 + arow) * AS_LD
                                    + acol + h * 16) * 2;
                ldsm_x4(ah[mi], ao);
            }
#pragma unroll
            for (int p = 0; p < 4; p++) {
                unsigned bo = sb + (GB_OFF + st * GB_STAGE + (h * 16 + brow) * BS_LD
                                    + wn * 64 + p * 16 + bcol) * 2;
                unsigned bf[4];
                ldsm_x4t(bf, bo);
#pragma unroll
                for (int mi = 0; mi < 2; mi++) {
                    mma_f16(oc[mi][2*p],   ah[mi], bf[0], bf[1]);
                    mma_f16(oc[mi][2*p+1], ah[mi], bf[2], bf[3]);
                }
            }
        }
        __syncthreads();
        st ^= 1;
    }

    const int g = lane >> 2, t = lane & 3;
#pragma unroll
    for (int mi = 0; mi < 2; mi++)
#pragma unroll
        for (int nt = 0; nt < 8; nt++) {
            int n = n0 + wn * 64 + nt * 8 + 2 * t;
            int m = m0 + wm * 32 + mi * 16 + g;
            if (MODE == 0) {
                int hh = n >> 6, d = n & 63;
                int b = m >> 11, s = m & (S_ - 1);
                size_t idx = ((size_t)(b * H_ + hh) * S_ + s) * DK_ + d;
                const float scale = (z == 0) ? 0.125f : 1.0f;
                __half* Dst = (z == 0) ? g_Qf : (z == 1) ? g_Kf : g_Vf;
                *(unsigned*)&Dst[idx] =
                    f16pack(oc[mi][nt][0] * scale, oc[mi][nt][1] * scale);
                *(unsigned*)&Dst[idx + 8 * DK_] =
                    f16pack(oc[mi][nt][2] * scale, oc[mi][nt][3] * scale);
            } else {
                *(float2*)&Out[(size_t)m * D_ + n] =
                    make_float2(oc[mi][nt][0], oc[mi][nt][1]);
                *(float2*)&Out[(size_t)(m + 8) * D_ + n] =
                    make_float2(oc[mi][nt][2], oc[mi][nt][3]);
            }
        }
}

// ---------------------------------------------------------------------------
// Flash attention: KV staged in 128-row tiles (two 64-row compute halves per
// stage, no sync between halves). Scores 1 MMA, PV 1 MMA.
// ---------------------------------------------------------------------------
#define KV_LD 72
#define KV_ARR 9216                       // elems, 128*72
#define KV_STAGE (2 * KV_ARR)             // K + V
#define ATTN_SMEM (2 * KV_STAGE * 2)      // 73728 B

__global__ __launch_bounds__(256) void attn_kernel() {
    extern __shared__ __align__(16) char smg[];
    __half* smh = (__half*)smg;
    const unsigned sb = sma(smg);
    const int tid = threadIdx.x, wid = tid >> 5, lane = tid & 31;
    const int g = lane >> 2, t = lane & 3;
    const int bh = blockIdx.y, q0 = blockIdx.x * 128;
    const size_t base = (size_t)bh * S_ * DK_;

    // hoist Q fragments
    unsigned qh[4][4];
    {
        for (int i = tid; i < 1024; i += 256) {
            int row = i >> 3, c8 = (i & 7) * 8;
            *(uint4*)&smh[row * KV_LD + c8] =
                *(const uint4*)&g_Qf[base + (size_t)(q0 + row) * DK_ + c8];
        }
        __syncthreads();
        unsigned ad = sb + ((wid * 16 + (lane & 15)) * KV_LD + (lane >> 4) * 8) * 2;
#pragma unroll
        for (int kt = 0; kt < 4; kt++)
            ldsm_x4(qh[kt], ad + kt * 32);
        __syncthreads();
    }

    float oc[8][4];
#pragma unroll
    for (int i = 0; i < 8; i++)
#pragma unroll
        for (int j = 0; j < 4; j++) oc[i][j] = 0.f;
    float m0r = -1e30f, m1r = -1e30f, l0r = 0.f, l1r = 0.f;

    const unsigned kb = (((lane & 7) + ((lane & 16) >> 1)) * KV_LD + (lane & 8)) * 2;
    const unsigned vb = ((lane & 15) * KV_LD + ((lane & 16) >> 1)) * 2;

    auto stage = [&](int kv0, int st) {
#pragma unroll
        for (int u = 0; u < 8; u++) {             // K,V: 128x64 each
            int arr = u >> 2, rem = tid + (u & 3) * 256;
            int row = rem >> 3, ch = (rem & 7) * 8;
            const __half* s = (arr == 0 ? g_Kf : g_Vf)
                + base + (size_t)(kv0 + row) * DK_ + ch;
            CP16(sb + (st * KV_STAGE + arr * KV_ARR + row * KV_LD + ch) * 2, s);
        }
    };

    stage(0, 0); CPCOMMIT();

    int st = 0;
    for (int kv0 = 0; kv0 < S_; kv0 += 128) {
        if (kv0 + 128 < S_) { stage(kv0 + 128, st ^ 1); CPCOMMIT(); CPWAIT1(); }
        else CPWAIT0();
        __syncthreads();

#pragma unroll
        for (int half = 0; half < 2; half++) {
            const unsigned hb = (unsigned)(half * 64 * KV_LD) * 2;
            const unsigned kK = sb + (st * KV_STAGE) * 2 + hb + kb;
            const unsigned vV = sb + (st * KV_STAGE + KV_ARR) * 2 + hb + vb;

            // ---- scores (64-wide) ----
            float sc[8][4];
#pragma unroll
            for (int i = 0; i < 8; i++)
#pragma unroll
                for (int j = 0; j < 4; j++) sc[i][j] = 0.f;
#pragma unroll
            for (int p = 0; p < 4; p++) {
#pragma unroll
                for (int kt = 0; kt < 4; kt++) {
                    unsigned off = (unsigned)(p * 16 * KV_LD + kt * 16) * 2;
                    unsigned kf[4];
                    ldsm_x4(kf, kK + off);
                    mma_f16(sc[2*p],   qh[kt], kf[0], kf[1]);
                    mma_f16(sc[2*p+1], qh[kt], kf[2], kf[3]);
                }
            }

            // ---- online softmax (rows g, g+8) ----
            float mx0 = sc[0][0], mx1 = sc[0][2];
#pragma unroll
            for (int nt = 0; nt < 8; nt++) {
                mx0 = fmaxf(mx0, fmaxf(sc[nt][0], sc[nt][1]));
                mx1 = fmaxf(mx1, fmaxf(sc[nt][2], sc[nt][3]));
            }
            mx0 = fmaxf(mx0, __shfl_xor_sync(0xffffffffu, mx0, 1));
            mx0 = fmaxf(mx0, __shfl_xor_sync(0xffffffffu, mx0, 2));
            mx1 = fmaxf(mx1, __shfl_xor_sync(0xffffffffu, mx1, 1));
            mx1 = fmaxf(mx1, __shfl_xor_sync(0xffffffffu, mx1, 2));
            float mn0 = fmaxf(m0r, mx0), mn1 = fmaxf(m1r, mx1);
            float cr0 = __expf(m0r - mn0), cr1 = __expf(m1r - mn1);
            m0r = mn0; m1r = mn1;
            float s0 = 0.f, s1 = 0.f;
#pragma unroll
            for (int nt = 0; nt < 8; nt++) {
                sc[nt][0] = __expf(sc[nt][0] - mn0);
                sc[nt][1] = __expf(sc[nt][1] - mn0);
                sc[nt][2] = __expf(sc[nt][2] - mn1);
                sc[nt][3] = __expf(sc[nt][3] - mn1);
                s0 += sc[nt][0] + sc[nt][1];
                s1 += sc[nt][2] + sc[nt][3];
            }
            s0 += __shfl_xor_sync(0xffffffffu, s0, 1);
            s0 += __shfl_xor_sync(0xffffffffu, s0, 2);
            s1 += __shfl_xor_sync(0xffffffffu, s1, 1);
            s1 += __shfl_xor_sync(0xffffffffu, s1, 2);
            l0r = l0r * cr0 + s0;
            l1r = l1r * cr1 + s1;
#pragma unroll
            for (int nt = 0; nt < 8; nt++) {
                oc[nt][0] *= cr0; oc[nt][1] *= cr0;
                oc[nt][2] *= cr1; oc[nt][3] *= cr1;
            }

            // ---- pack P ----
            unsigned pa[4][4];
#pragma unroll
            for (int kt = 0; kt < 4; kt++) {
                int j0 = 2 * kt, j1 = 2 * kt + 1;
                pa[kt][0] = f16pack(sc[j0][0], sc[j0][1]);
                pa[kt][1] = f16pack(sc[j0][2], sc[j0][3]);
                pa[kt][2] = f16pack(sc[j1][0], sc[j1][1]);
                pa[kt][3] = f16pack(sc[j1][2], sc[j1][3]);
            }

            // ---- PV ----
#pragma unroll
            for (int p = 0; p < 4; p++) {
#pragma unroll
                for (int kt = 0; kt < 4; kt++) {
                    unsigned off = (unsigned)(kt * 16 * KV_LD + p * 16) * 2;
                    unsigned vf[4];
                    ldsm_x4t(vf, vV + off);
                    mma_f16(oc[2*p],   pa[kt], vf[0], vf[1]);
                    mma_f16(oc[2*p+1], pa[kt], vf[2], vf[3]);
                }
            }
        }
        __syncthreads();
        st ^= 1;
    }

    const float i0 = 1.f / l0r, i1 = 1.f / l1r;
    const int r = q0 + wid * 16 + g;
#pragma unroll
    for (int nt = 0; nt < 8; nt++) {
        int d = nt * 8 + 2 * t;
        *(unsigned*)&g_Of[base + (size_t)r * DK_ + d] =
            f16pack(oc[nt][0] * i0, oc[nt][1] * i0);
        *(unsigned*)&g_Of[base + (size_t)(r + 8) * DK_ + d] =
            f16pack(oc[nt][2] * i1, oc[nt][3] * i1);
    }
}

// ---------------------------------------------------------------------------
extern "C" void kernel_launch(void* const* d_in, const int* in_sizes, int n_in,
                              void* d_out, int out_size)
{
    const float* x  = (const float*)d_in[0];
    const float* WQ = (const float*)d_in[1];
    const float* WK = (const float*)d_in[2];
    const float* WV = (const float*)d_in[3];
    const float* WO = (const float*)d_in[4];
    float* out = (float*)d_out;

    (void)in_sizes; (void)n_in; (void)out_size;

    cudaFuncSetAttribute(gemm_kernel<0>,
        cudaFuncAttributeMaxDynamicSharedMemorySize, GEMM_SMEM);
    cudaFuncSetAttribute(gemm_kernel<1>,
        cudaFuncAttributeMaxDynamicSharedMemorySize, GEMM_SMEM);
    cudaFuncSetAttribute(attn_kernel,
        cudaFuncAttributeMaxDynamicSharedMemorySize, ATTN_SMEM);

    conv_x_kernel<<<M_ * D_ / 8 / 256, 256>>>(x);
    conv_wqkv_kernel<<<3 * D_ * D_ / 8 / 256, 256>>>(WQ, WK, WV);
    conv_wo_kernel<<<D_ * D_ / 8 / 256, 256>>>(WO);

    gemm_kernel<0><<<dim3(D_ / 128, M_ / 128, 3), 256, GEMM_SMEM>>>(nullptr);
    attn_kernel<<<dim3(S_ / 128, BH_), 256, ATTN_SMEM>>>();
    gemm_kernel<1><<<dim3(D_ / 128, M_ / 128), 256, GEMM_SMEM>>>(out);
}